// round 17
// baseline (speedup 1.0000x reference)
#include <cuda_runtime.h>
#include <cuda_fp16.h>
#include <math.h>
#include <stdint.h>
#include <mma.h>

using namespace nvcuda;

#define BB 1024
#define TT 512
#define CTXN 23
#define DD 320
#define LL 5
#define HH 8
#define FFN 1280
#define NM 49      // NMODES+1
#define SS 24      // CLS + 23 tokens
#define DHD 40
#define MTOT (BB * SS)   // 24576

// ------------------------------------------------------------------
// Global scratch
// ------------------------------------------------------------------
__device__ float  g_x[MTOT * DD];      // residual stream (fp32)
__device__ __half g_hh[MTOT * DD];     // LN / attn outputs (fp16, GEMM A)
__device__ __half g_qkv[MTOT * 3*DD];  // qkv (fp16)
__device__ __half g_bh[MTOT * FFN];    // ffn hidden (fp16, GEMM A)
// fp16 weight copies: W_in | W_out | W1 | W2
#define WR_WIN  0
#define WR_WOUT 1536000
#define WR_W1   2048000
#define WR_W2   4096000
#define WR_TOT  6144000
__device__ __half g_wh[WR_TOT];

__device__ __forceinline__ uint32_t smem_u32(const void* p) {
    uint32_t a;
    asm("{ .reg .u64 t; cvta.to.shared.u64 t, %1; cvt.u32.u64 %0, t; }"
        : "=r"(a) : "l"(p));
    return a;
}
__device__ __forceinline__ void cp_async16(uint32_t s, const void* g) {
    asm volatile("cp.async.cg.shared.global [%0], [%1], 16;" :: "r"(s), "l"(g));
}
#define CP_COMMIT() asm volatile("cp.async.commit_group;" ::: "memory")
#define CP_WAIT(n)  asm volatile("cp.async.wait_group %0;" :: "n"(n) : "memory")

// ------------------------------------------------------------------
// wmma fp16 GEMM (fp32 accumulate), K compile-time:
//   C[m,n] = act( A[m,:].B[n,:] + bias[n] ) (+ R[m,n])
// 256 x 64 x 64 block tile, 8 warps in 4x2 -> 64x32 warp tiles, 2 stages.
// ------------------------------------------------------------------
#define BM 256
#define BN 64
#define BK 64
#define ASTR 72                                  // halves (144 B rows)
#define BSTR 72
#define CSTR 68                                  // floats (epilogue staging)
#define A_BUF (BM * ASTR)
#define B_BUF (BN * BSTR)
#define STAGE_H (A_BUF + B_BUF)                  // 23040 halves
#define GSM_BYTES (2 * STAGE_H * 2)              // 92160 B

template<int ACT, int RES, int KK, typename OutT>
__global__ void __launch_bounds__(256, 2)
gemm_h(const __half* __restrict__ A, const __half* __restrict__ B,
       const float* __restrict__ bias, const float* __restrict__ R,
       OutT* __restrict__ C, int N)
{
    extern __shared__ __align__(16) char smraw[];
    __half* smh = (__half*)smraw;
    const int tid = threadIdx.x;
    const int wid = tid >> 5;
    const int wm = wid >> 1;
    const int wn = wid & 1;
    const int mbase = blockIdx.x * BM;
    const int nbase = blockIdx.y * BN;
    constexpr int KT = KK / BK;

    wmma::fragment<wmma::accumulator, 16, 16, 16, float> acc[4][2];
    #pragma unroll
    for (int i = 0; i < 4; i++)
        #pragma unroll
        for (int j = 0; j < 2; j++) wmma::fill_fragment(acc[i][j], 0.0f);

    uint32_t sbase = smem_u32(smraw);
    const int arow = tid >> 3, ac8 = tid & 7;

    auto load_tile = [&](int kt, int buf) {
        const __half* Ag = A + (size_t)mbase * KK + kt * BK;
        const __half* Bg = B + (size_t)nbase * KK + kt * BK;
        uint32_t sA = sbase + (uint32_t)(buf * STAGE_H) * 2;
        uint32_t sB = sA + (uint32_t)A_BUF * 2;
        #pragma unroll
        for (int t = 0; t < 8; t++) {
            int row = t * 32 + arow;
            cp_async16(sA + (uint32_t)(row * ASTR + ac8 * 8) * 2,
                       Ag + (size_t)row * KK + ac8 * 8);
        }
        #pragma unroll
        for (int t = 0; t < 2; t++) {
            int row = t * 32 + arow;
            cp_async16(sB + (uint32_t)(row * BSTR + ac8 * 8) * 2,
                       Bg + (size_t)row * KK + ac8 * 8);
        }
        CP_COMMIT();
    };

    load_tile(0, 0);

    #pragma unroll
    for (int kt = 0; kt < KT; kt++) {
        const int cur = kt & 1;
        if (kt + 1 < KT) { load_tile(kt + 1, 1 - cur); CP_WAIT(1); }
        else             { CP_WAIT(0); }
        __syncthreads();

        const __half* Ab = smh + cur * STAGE_H + wm * 64 * ASTR;
        const __half* Bb = smh + cur * STAGE_H + A_BUF + wn * 32 * BSTR;
        #pragma unroll
        for (int k0 = 0; k0 < BK; k0 += 16) {
            wmma::fragment<wmma::matrix_a, 16, 16, 16, __half, wmma::row_major> af[4];
            wmma::fragment<wmma::matrix_b, 16, 16, 16, __half, wmma::col_major> bf[2];
            #pragma unroll
            for (int j = 0; j < 2; j++)
                wmma::load_matrix_sync(bf[j], Bb + j * 16 * BSTR + k0, BSTR);
            #pragma unroll
            for (int i = 0; i < 4; i++) {
                wmma::load_matrix_sync(af[i], Ab + i * 16 * ASTR + k0, ASTR);
                #pragma unroll
                for (int j = 0; j < 2; j++)
                    wmma::mma_sync(acc[i][j], af[i], bf[j], acc[i][j]);
            }
        }
        __syncthreads();
    }

    // epilogue
    float* Cs = (float*)smraw;
    #pragma unroll
    for (int i = 0; i < 4; i++)
        #pragma unroll
        for (int j = 0; j < 2; j++)
            wmma::store_matrix_sync(Cs + (wm * 64 + i * 16) * CSTR + wn * 32 + j * 16,
                                    acc[i][j], CSTR, wmma::mem_row_major);
    __syncthreads();

    #pragma unroll 8
    for (int idx = tid; idx < BM * BN; idx += 256) {
        int r = idx >> 6, c = idx & 63;
        float v = Cs[r * CSTR + c] + bias[nbase + c];
        if (ACT) v = 0.5f * v * (1.f + erff(v * 0.70710678118654752f));
        size_t gi = (size_t)(mbase + r) * N + nbase + c;
        if (RES) v += R[gi];
        if (sizeof(OutT) == 2) C[gi] = (OutT)__float2half_rn(v);
        else                   C[gi] = (OutT)v;
    }
}

// ------------------------------------------------------------------
// Fused weight conversion fp32 -> fp16 (float4 in, 2x half2 out)
// Regions (in float4 units): W_in 384000 | W_out 128000 | W1 512000 | W2 512000
// ------------------------------------------------------------------
#define CV_TOT4 1536000
__global__ void __launch_bounds__(256)
convw(const float* __restrict__ s1, const float* __restrict__ s2,
      const float* __restrict__ s3, const float* __restrict__ s4,
      __half* __restrict__ d)
{
    int i = blockIdx.x * 256 + threadIdx.x;
    if (i >= CV_TOT4) return;
    const float* s; int o4;
    if (i < 384000)       { s = s1; o4 = i; }
    else if (i < 512000)  { s = s2; o4 = i - 384000; }
    else if (i < 1024000) { s = s3; o4 = i - 512000; }
    else                  { s = s4; o4 = i - 1024000; }
    float4 v = ((const float4*)s)[o4];
    __half2* dp = (__half2*)d;
    dp[i * 2]     = __floats2half2_rn(v.x, v.y);
    dp[i * 2 + 1] = __floats2half2_rn(v.z, v.w);
}

// ------------------------------------------------------------------
// Elementwise / small kernels
// ------------------------------------------------------------------
__global__ void __launch_bounds__(256)
embed_kernel(const float* __restrict__ ctx, const float* __restrict__ W_e,
             const float* __restrict__ b_e, const float* __restrict__ cls,
             float* __restrict__ X)
{
    int i = blockIdx.x * 256 + threadIdx.x;
    int d = i % DD;
    int s = (i / DD) % SS;
    int b = i / (DD * SS);
    float v;
    if (s == 0) v = cls[d];
    else        v = ctx[b * CTXN + (s - 1)] * W_e[d] + b_e[d];
    X[i] = v;
}

// one warp per row of 320; float2 loads, half2 stores
__global__ void __launch_bounds__(256)
ln_kernel(const float* __restrict__ X, const float* __restrict__ w,
          const float* __restrict__ b, __half* __restrict__ O)
{
    int row = blockIdx.x * 8 + (threadIdx.x >> 5);
    int lane = threadIdx.x & 31;
    const float2* xr = (const float2*)(X + (size_t)row * DD);
    float2 v[5];
    float sum = 0.f, sq = 0.f;
    #pragma unroll
    for (int i = 0; i < 5; i++) {
        v[i] = xr[lane + i * 32];
        sum += v[i].x + v[i].y;
        sq  += v[i].x * v[i].x + v[i].y * v[i].y;
    }
    #pragma unroll
    for (int o = 16; o > 0; o >>= 1) {
        sum += __shfl_xor_sync(0xffffffffu, sum, o);
        sq  += __shfl_xor_sync(0xffffffffu, sq, o);
    }
    float mean = sum * (1.f / DD);
    float var  = sq * (1.f / DD) - mean * mean;
    float inv  = rsqrtf(var + 1e-5f);
    __half2* orow = (__half2*)(O + (size_t)row * DD);
    const float2* w2 = (const float2*)w;
    const float2* b2 = (const float2*)b;
    #pragma unroll
    for (int i = 0; i < 5; i++) {
        int k2 = lane + i * 32;
        float2 wv = w2[k2], bv = b2[k2];
        orow[k2] = __floats2half2_rn((v[i].x - mean) * inv * wv.x + bv.x,
                                     (v[i].y - mean) * inv * wv.y + bv.y);
    }
}

// attention for one batch element, fp16 qkv in smem, fp32 scores.
#define QSTH 968   // half stride per row (1936 B, 16B-aligned)
#define ATTN_SMEM (SS * QSTH * 2 + HH * SS * SS * 4)
__global__ void __launch_bounds__(256)
attn_kernel(const __half* __restrict__ qkv, __half* __restrict__ o)
{
    extern __shared__ __align__(16) char smc[];
    __half* t  = (__half*)smc;                       // [24][QSTH]
    float*  sc = (float*)(smc + SS * QSTH * 2);      // [8*24*24]
    const int b = blockIdx.x, tid = threadIdx.x;

    const float4* src = (const float4*)(qkv + (size_t)b * SS * 960);
    for (int i = tid; i < SS * 120; i += 256) {
        int r = i / 120, c = i - r * 120;
        *(float4*)(t + r * QSTH + c * 8) = src[r * 120 + c];
    }
    __syncthreads();

    for (int idx = tid; idx < HH * SS * SS; idx += 256) {
        int h = idx / (SS * SS);
        int rem = idx - h * (SS * SS);
        int i = rem / SS, j = rem - i * SS;
        const __half2* q = (const __half2*)(t + i * QSTH + h * DHD);
        const __half2* k = (const __half2*)(t + j * QSTH + DD + h * DHD);
        float s = 0.f;
        #pragma unroll
        for (int d = 0; d < DHD / 2; d++) {
            float2 qf = __half22float2(q[d]);
            float2 kf = __half22float2(k[d]);
            s += qf.x * kf.x + qf.y * kf.y;
        }
        sc[idx] = s * 0.15811388300841897f;
    }
    __syncthreads();

    if (tid < HH * SS) {
        float* row = sc + tid * SS;
        float mx = row[0];
        #pragma unroll
        for (int j = 1; j < SS; j++) mx = fmaxf(mx, row[j]);
        float sum = 0.f;
        #pragma unroll
        for (int j = 0; j < SS; j++) { float e = expf(row[j] - mx); row[j] = e; sum += e; }
        float inv = 1.f / sum;
        #pragma unroll
        for (int j = 0; j < SS; j++) row[j] *= inv;
    }
    __syncthreads();

    // o[i, d2*2 .. d2*2+1] — two columns per thread via half2
    for (int idx = tid; idx < SS * (DD / 2); idx += 256) {
        int i = idx / (DD / 2), d2 = idx - i * (DD / 2);
        int h = (d2 * 2) / DHD;
        const float* a = sc + (h * SS + i) * SS;
        float ax = 0.f, ay = 0.f;
        #pragma unroll
        for (int j = 0; j < SS; j++) {
            float2 vf = __half22float2(*(const __half2*)(t + j * QSTH + 2 * DD + d2 * 2));
            ax += a[j] * vf.x;
            ay += a[j] * vf.y;
        }
        *(__half2*)(o + (size_t)(b * SS + i) * DD + d2 * 2) = __floats2half2_rn(ax, ay);
    }
}

// CLS head + chebyshev + sigmoid, one block per batch element
__global__ void __launch_bounds__(320)
head_cheb_kernel(const float* __restrict__ X,
                 const float* __restrict__ hln_w, const float* __restrict__ hln_b,
                 const float* __restrict__ Wh1,   const float* __restrict__ bh1,
                 const float* __restrict__ Wh2,   const float* __restrict__ bh2,
                 const float* __restrict__ k_norm, float* __restrict__ out)
{
    __shared__ float hbuf[DD], scr[DD], carr[NM], wsum[10], wsq[10], red[2];
    const int b = blockIdx.x, tid = threadIdx.x;
    const float* xr = X + (size_t)b * SS * DD;

    float v = xr[tid];
    float sum = v, sq = v * v;
    #pragma unroll
    for (int o = 16; o > 0; o >>= 1) {
        sum += __shfl_xor_sync(0xffffffffu, sum, o);
        sq  += __shfl_xor_sync(0xffffffffu, sq, o);
    }
    int wid = tid >> 5, lane = tid & 31;
    if (lane == 0) { wsum[wid] = sum; wsq[wid] = sq; }
    __syncthreads();
    if (tid == 0) {
        float s = 0.f, q = 0.f;
        #pragma unroll
        for (int w = 0; w < 10; w++) { s += wsum[w]; q += wsq[w]; }
        float mean = s * (1.f / DD);
        float var  = q * (1.f / DD) - mean * mean;
        red[0] = mean; red[1] = rsqrtf(var + 1e-5f);
    }
    __syncthreads();
    hbuf[tid] = (v - red[0]) * red[1] * hln_w[tid] + hln_b[tid];
    __syncthreads();

    {
        const float4* Wr = (const float4*)(Wh1 + (size_t)tid * DD);
        float acc = 0.f;
        #pragma unroll 4
        for (int k4 = 0; k4 < DD / 4; k4++) {
            float4 w = Wr[k4];
            float4 a = ((const float4*)hbuf)[k4];
            acc += a.x * w.x + a.y * w.y + a.z * w.z + a.w * w.w;
        }
        acc += bh1[tid];
        scr[tid] = 0.5f * acc * (1.f + erff(acc * 0.70710678118654752f));
    }
    __syncthreads();

    if (tid < NM) {
        const float4* Wr = (const float4*)(Wh2 + (size_t)tid * DD);
        float acc = 0.f;
        #pragma unroll 4
        for (int k4 = 0; k4 < DD / 4; k4++) {
            float4 w = Wr[k4];
            float4 a = ((const float4*)scr)[k4];
            acc += a.x * w.x + a.y * w.y + a.z * w.z + a.w * w.w;
        }
        carr[tid] = acc + bh2[tid];
    }
    __syncthreads();

    for (int t = tid; t < TT; t += 320) {
        float xx = k_norm[b * TT + t];
        float tp = 1.f, tc = xx;
        float acc = carr[0] + carr[1] * xx;
        float x2 = 2.f * xx;
        #pragma unroll
        for (int n = 2; n < NM; n++) {
            float tn = x2 * tc - tp;
            acc += carr[n] * tn;
            tp = tc; tc = tn;
        }
        out[b * TT + t] = 1.f / (1.f + expf(-acc));
    }
}

// ------------------------------------------------------------------
// Host
// ------------------------------------------------------------------
extern "C" void kernel_launch(void* const* d_in, const int* in_sizes, int n_in,
                              void* d_out, int out_size)
{
    const float* k_norm = (const float*)d_in[0];
    const float* ctx    = (const float*)d_in[1];
    const float* W_e    = (const float*)d_in[2];
    const float* b_e    = (const float*)d_in[3];
    const float* cls    = (const float*)d_in[4];
    const float* ln1_w  = (const float*)d_in[5];
    const float* ln1_b  = (const float*)d_in[6];
    const float* W_in   = (const float*)d_in[7];
    const float* b_in   = (const float*)d_in[8];
    const float* W_out  = (const float*)d_in[9];
    const float* b_out  = (const float*)d_in[10];
    const float* ln2_w  = (const float*)d_in[11];
    const float* ln2_b  = (const float*)d_in[12];
    const float* W1     = (const float*)d_in[13];
    const float* b1     = (const float*)d_in[14];
    const float* W2     = (const float*)d_in[15];
    const float* b2     = (const float*)d_in[16];
    const float* hln_w  = (const float*)d_in[17];
    const float* hln_b  = (const float*)d_in[18];
    const float* Wh1    = (const float*)d_in[19];
    const float* bh1    = (const float*)d_in[20];
    const float* Wh2    = (const float*)d_in[21];
    const float* bh2    = (const float*)d_in[22];

    float *px;
    __half *phh, *pqkv, *pbh, *pwh;
    cudaGetSymbolAddress((void**)&px,   g_x);
    cudaGetSymbolAddress((void**)&phh,  g_hh);
    cudaGetSymbolAddress((void**)&pqkv, g_qkv);
    cudaGetSymbolAddress((void**)&pbh,  g_bh);
    cudaGetSymbolAddress((void**)&pwh,  g_wh);

    cudaFuncSetAttribute((void*)gemm_h<0,0,DD,__half>,  cudaFuncAttributeMaxDynamicSharedMemorySize, GSM_BYTES);
    cudaFuncSetAttribute((void*)gemm_h<0,1,DD,float>,   cudaFuncAttributeMaxDynamicSharedMemorySize, GSM_BYTES);
    cudaFuncSetAttribute((void*)gemm_h<1,0,DD,__half>,  cudaFuncAttributeMaxDynamicSharedMemorySize, GSM_BYTES);
    cudaFuncSetAttribute((void*)gemm_h<0,1,FFN,float>,  cudaFuncAttributeMaxDynamicSharedMemorySize, GSM_BYTES);
    cudaFuncSetAttribute((void*)attn_kernel,            cudaFuncAttributeMaxDynamicSharedMemorySize, ATTN_SMEM);

    convw<<<(CV_TOT4 + 255) / 256, 256>>>(W_in, W_out, W1, W2, pwh);
    embed_kernel<<<MTOT * DD / 256, 256>>>(ctx, W_e, b_e, cls, px);

    for (int l = 0; l < LL; l++) {
        ln_kernel<<<MTOT / 8, 256>>>(px, ln1_w + l * DD, ln1_b + l * DD, phh);
        gemm_h<0,0,DD,__half><<<dim3(MTOT / BM, 960 / BN), 256, GSM_BYTES>>>(
            phh, pwh + WR_WIN + (size_t)l * 3 * DD * DD, b_in + l * 3 * DD, nullptr,
            pqkv, 3 * DD);
        attn_kernel<<<BB, 256, ATTN_SMEM>>>(pqkv, phh);
        gemm_h<0,1,DD,float><<<dim3(MTOT / BM, DD / BN), 256, GSM_BYTES>>>(
            phh, pwh + WR_WOUT + (size_t)l * DD * DD, b_out + l * DD, px,
            px, DD);
        ln_kernel<<<MTOT / 8, 256>>>(px, ln2_w + l * DD, ln2_b + l * DD, phh);
        gemm_h<1,0,DD,__half><<<dim3(MTOT / BM, FFN / BN), 256, GSM_BYTES>>>(
            phh, pwh + WR_W1 + (size_t)l * FFN * DD, b1 + l * FFN, nullptr,
            pbh, FFN);
        gemm_h<0,1,FFN,float><<<dim3(MTOT / BM, DD / BN), 256, GSM_BYTES>>>(
            pbh, pwh + WR_W2 + (size_t)l * DD * FFN, b2 + l * DD, px,
            px, DD);
    }

    head_cheb_kernel<<<BB, 320>>>(px, hln_w, hln_b, Wh1, bh1, Wh2, bh2,
                                  k_norm, (float*)d_out);
}